// round 8
// baseline (speedup 1.0000x reference)
#include <cuda_runtime.h>
#include <cstdint>

#define BB 2
#define LL 1024
#define HH 768
#define DI 1536
#define NSTATE 16
#define KCONV 4
#define RR 48
#define MM (BB*LL)          // 2048
#define D1 (2*DI*4)         // 12288
#define D2 (2*DI)           // 3072
#define D3 (4*DI)           // 6144
#define NSPLIT 8

// ---------------- scratch (device globals: no allocation allowed) --------------
// fp32 buffers
__device__ float g_P [(size_t)MM*D2];
__device__ float g_HS[(size_t)MM*DI];
__device__ float g_SPX[(size_t)NSPLIT*MM*128];
__device__ float g_SSMP[(size_t)MM*128];
__device__ float g_DT[(size_t)MM*DI];
__device__ float g_YS[(size_t)MM*DI];
// bf16 hi/lo pairs, stored as packed u32 (2 bf16 per u32), elem count /2
__device__ uint32_t g_xh [(size_t)MM*HH/2],  g_xl [(size_t)MM*HH/2];
__device__ uint32_t g_iuwh[(size_t)D1*HH/2], g_iuwl[(size_t)D1*HH/2];
__device__ uint32_t g_idwh[(size_t)D2*D1/2], g_idwl[(size_t)D2*D1/2];
__device__ uint32_t g_ouwh[(size_t)D3*DI/2], g_ouwl[(size_t)D3*DI/2];
__device__ uint32_t g_odwh[(size_t)HH*D3/2], g_odwl[(size_t)HH*D3/2];
__device__ uint32_t g_T1h[(size_t)MM*D1/2],  g_T1l[(size_t)MM*D1/2];
__device__ uint32_t g_T4h[(size_t)MM*D3/2],  g_T4l[(size_t)MM*D3/2];
__device__ uint32_t g_Yh [(size_t)MM*DI/2],  g_Yl [(size_t)MM*DI/2];
__device__ uint32_t g_HSh[(size_t)MM*DI/2],  g_HSl[(size_t)MM*DI/2];
__device__ uint32_t g_XPWh[128*DI/2],        g_XPWl[128*DI/2];

__device__ __forceinline__ float siluf(float x) { return x / (1.f + __expf(-x)); }
__device__ __forceinline__ float softplusf(float x) { return (x > 20.f) ? x : log1pf(__expf(x)); }

// split two fp32 -> packed bf16x2 hi (exact truncation) + bf16x2 lo (residual)
__device__ __forceinline__ void split2(float a, float b, uint32_t& hi, uint32_t& lo) {
    uint32_t x = __float_as_uint(a), y = __float_as_uint(b);
    asm("prmt.b32 %0, %1, %2, 0x7632;" : "=r"(hi) : "r"(x), "r"(y));
    float lx = a - __uint_as_float(x & 0xFFFF0000u);
    float ly = b - __uint_as_float(y & 0xFFFF0000u);
    asm("cvt.rn.satfinite.bf16x2.f32 %0, %1, %2;" : "=r"(lo) : "f"(ly), "f"(lx));
}

__device__ __forceinline__ uint32_t smem_u32(const void* p) {
    uint32_t a;
    asm("{ .reg .u64 t; cvta.to.shared.u64 t, %1; cvt.u32.u64 %0, t; }" : "=r"(a) : "l"(p));
    return a;
}
__device__ __forceinline__ void ldsm4(uint32_t* r, uint32_t addr) {
    asm volatile("ldmatrix.sync.aligned.m8n8.x4.shared.b16 {%0,%1,%2,%3}, [%4];"
        : "=r"(r[0]), "=r"(r[1]), "=r"(r[2]), "=r"(r[3]) : "r"(addr));
}
__device__ __forceinline__ void mma_bf16(float* d, const uint32_t* a, const uint32_t* b) {
    asm volatile("mma.sync.aligned.m16n8k16.row.col.f32.bf16.bf16.f32 "
        "{%0,%1,%2,%3}, {%4,%5,%6,%7}, {%8,%9}, {%0,%1,%2,%3};"
        : "+f"(d[0]), "+f"(d[1]), "+f"(d[2]), "+f"(d[3])
        : "r"(a[0]), "r"(a[1]), "r"(a[2]), "r"(a[3]), "r"(b[0]), "r"(b[1]));
}
__device__ __forceinline__ void cpa16(uint32_t dst, const uint32_t* src) {
    asm volatile("cp.async.cg.shared.global [%0], [%1], 16;" :: "r"(dst), "l"(src) : "memory");
}

// ---------------- split pass: fp32 -> hi/lo bf16 pairs -------------------------
__global__ void split_kernel(const float* __restrict__ src, uint32_t* __restrict__ hi,
                             uint32_t* __restrict__ lo, int n4)
{
    int i = blockIdx.x * blockDim.x + threadIdx.x;
    if (i >= n4) return;
    float4 v = ((const float4*)src)[i];
    uint32_t h0, l0, h1, l1;
    split2(v.x, v.y, h0, l0);
    split2(v.z, v.w, h1, l1);
    ((uint2*)hi)[i] = make_uint2(h0, h1);
    ((uint2*)lo)[i] = make_uint2(l0, l1);
}

// ================= HMMA bf16 split GEMM: C = epi(A @ W^T) ======================
// Inputs pre-split to bf16 hi/lo. CTA 128x128, 256 thr, K-chunk = 32 elems.
// cp.async 4-stage pipeline. smem row: 32 bf16 = 64B padded to 80B.
#define NST 4
#define ROWB 80u
#define TILEB (128u * ROWB)          // 10240
#define BUFB  (4u * TILEB)           // 40960
#define HSMEM (NST * BUFB)           // 163840

template<int EPI>   // 0: fp32 out, 2: silu + hi/lo bf16 out
__global__ void __launch_bounds__(256, 1) hgemm_kernel(
    const uint32_t* __restrict__ Ah, const uint32_t* __restrict__ Al,
    const uint32_t* __restrict__ Wh, const uint32_t* __restrict__ Wl,
    float* __restrict__ Cf, uint32_t* __restrict__ Ch, uint32_t* __restrict__ Cl,
    int lda, int ldw, int ldc, int kPerSplit, long csplit)
{
    extern __shared__ char smem[];
    const uint32_t sb = smem_u32(smem);
    const int tid = threadIdx.x;
    const long bm = (long)blockIdx.y * 128;
    const long bn = (long)blockIdx.x * 128;
    const int koff = blockIdx.z * kPerSplit;
    float* Cout = Cf + (long)blockIdx.z * csplit;

    // producer: thread t copies row r=t>>1, 32B-half (t&1) of each 64B tile row
    const int r = tid >> 1, half = tid & 1;
    const uint32_t soff = (uint32_t)r * ROWB + (uint32_t)half * 32u;
    const long aoff = ((bm + r) * (long)lda + koff) / 2 + half * 8;
    const long woff = ((bn + r) * (long)ldw + koff) / 2 + half * 8;
    const uint32_t* pAh = Ah + aoff;  const uint32_t* pAl = Al + aoff;
    const uint32_t* pWh = Wh + woff;  const uint32_t* pWl = Wl + woff;

#define ISSUE(tt) { long co = (long)(tt) * 16; uint32_t stb = sb + (uint32_t)((tt) & (NST-1)) * BUFB; \
    cpa16(stb + 0*TILEB + soff, pAh + co); cpa16(stb + 0*TILEB + soff + 16, pAh + co + 4); \
    cpa16(stb + 1*TILEB + soff, pAl + co); cpa16(stb + 1*TILEB + soff + 16, pAl + co + 4); \
    cpa16(stb + 2*TILEB + soff, pWh + co); cpa16(stb + 2*TILEB + soff + 16, pWh + co + 4); \
    cpa16(stb + 3*TILEB + soff, pWl + co); cpa16(stb + 3*TILEB + soff + 16, pWl + co + 4); \
    asm volatile("cp.async.commit_group;" ::: "memory"); }

    // consumer indexing (8 warps 4x2, warp tile 32x64)
    const int wid = tid >> 5, lane = tid & 31;
    const int wm = wid >> 1, wn = wid & 1;
    const uint32_t a_addr = (uint32_t)((wm * 32 + (lane & 15)) * ROWB + ((lane >> 4) << 3) * 2);
    const uint32_t b_row  = (uint32_t)(wn * 64 + (lane & 7) + ((lane >> 4) & 1) * 8);
    const uint32_t b_addr = b_row * ROWB + (uint32_t)(((lane >> 3) & 1) * 16);

    float acc[2][8][4];
#pragma unroll
    for (int f = 0; f < 2; f++)
#pragma unroll
        for (int g = 0; g < 8; g++)
#pragma unroll
            for (int e = 0; e < 4; e++) acc[f][g][e] = 0.f;

    const int Tc = kPerSplit >> 5;

    ISSUE(0); ISSUE(1); ISSUE(2);

    for (int t = 0; t < Tc; t++) {
        asm volatile("cp.async.wait_group 2;" ::: "memory");
        __syncthreads();
        if (t + 3 < Tc) ISSUE(t + 3);

        const uint32_t base = sb + (uint32_t)(t & (NST-1)) * BUFB;
#pragma unroll
        for (int s = 0; s < 2; s++) {
            uint32_t ah[2][4], al[2][4];
#pragma unroll
            for (int f = 0; f < 2; f++) {
                uint32_t ad = base + a_addr + (uint32_t)(f * 16) * ROWB + (uint32_t)(s * 32);
                ldsm4(ah[f], ad);
                ldsm4(al[f], ad + TILEB);
            }
            uint32_t bh[8][2], bl[8][2];
#pragma unroll
            for (int g2 = 0; g2 < 4; g2++) {
                uint32_t bd = base + 2 * TILEB + b_addr + (uint32_t)(g2 * 16) * ROWB + (uint32_t)(s * 32);
                uint32_t q[4];
                ldsm4(q, bd);
                bh[2*g2][0] = q[0]; bh[2*g2][1] = q[1];
                bh[2*g2+1][0] = q[2]; bh[2*g2+1][1] = q[3];
                ldsm4(q, bd + TILEB);
                bl[2*g2][0] = q[0]; bl[2*g2][1] = q[1];
                bl[2*g2+1][0] = q[2]; bl[2*g2+1][1] = q[3];
            }
#pragma unroll
            for (int f = 0; f < 2; f++)
#pragma unroll
                for (int g = 0; g < 8; g++) {
                    mma_bf16(acc[f][g], ah[f], bh[g]);
                    mma_bf16(acc[f][g], ah[f], bl[g]);
                    mma_bf16(acc[f][g], al[f], bh[g]);
                }
        }
        __syncthreads();
    }
#undef ISSUE

    // epilogue
#pragma unroll
    for (int f = 0; f < 2; f++) {
        const long row = bm + wm * 32 + f * 16 + (lane >> 2);
#pragma unroll
        for (int g = 0; g < 8; g++) {
            const long col = bn + wn * 64 + g * 8 + (lane & 3) * 2;
            float2 v0 = {acc[f][g][0], acc[f][g][1]};
            float2 v1 = {acc[f][g][2], acc[f][g][3]};
            if (EPI == 2) {
                v0.x = siluf(v0.x); v0.y = siluf(v0.y);
                v1.x = siluf(v1.x); v1.y = siluf(v1.y);
                uint32_t h, l;
                split2(v0.x, v0.y, h, l);
                Ch[(row * (long)ldc + col) >> 1] = h;
                Cl[(row * (long)ldc + col) >> 1] = l;
                split2(v1.x, v1.y, h, l);
                Ch[((row + 8) * (long)ldc + col) >> 1] = h;
                Cl[((row + 8) * (long)ldc + col) >> 1] = l;
            } else {
                *(float2*)&Cout[row * (long)ldc + col] = v0;
                *(float2*)&Cout[(row + 8) * (long)ldc + col] = v1;
            }
        }
    }
}

// ================= scalar FFMA2 sgemm (dt GEMM, K=48) ==========================
template<int EPI>
__global__ void __launch_bounds__(256) sgemm_kernel(
    const float* __restrict__ A, const float* __restrict__ W,
    const float* __restrict__ bias, float* __restrict__ C,
    int K, int lda, int ldw, int ldc)
{
    __shared__ __align__(16) float As[2][8][128];
    __shared__ __align__(16) float Bs[2][8][128];

    const int tid = threadIdx.x;
    const long bm = (long)blockIdx.y * 128;
    const long bn = (long)blockIdx.x * 128;
    const int tx = tid & 15;
    const int ty = tid >> 4;
    const int lr = tid >> 1;
    const int lc = (tid & 1) * 4;

    const float* Ap = A + (bm + lr) * (long)lda + lc;
    const float* Wp = W + (bn + lr) * (long)ldw + lc;

    unsigned long long acc[8][4];
#pragma unroll
    for (int i = 0; i < 8; i++)
#pragma unroll
        for (int j = 0; j < 4; j++) acc[i][j] = 0ULL;

    const int T = K >> 3;
    float4 av = *(const float4*)(Ap);
    float4 wv = *(const float4*)(Wp);
    As[0][lc + 0][lr] = av.x; As[0][lc + 1][lr] = av.y;
    As[0][lc + 2][lr] = av.z; As[0][lc + 3][lr] = av.w;
    Bs[0][lc + 0][lr] = wv.x; Bs[0][lc + 1][lr] = wv.y;
    Bs[0][lc + 2][lr] = wv.z; Bs[0][lc + 3][lr] = wv.w;
    if (T > 1) { av = *(const float4*)(Ap + 8); wv = *(const float4*)(Wp + 8); }
    __syncthreads();

    int p = 0;
    for (int t = 0; t < T; t++) {
        if (t + 1 < T) {
            int q = p ^ 1;
            As[q][lc + 0][lr] = av.x; As[q][lc + 1][lr] = av.y;
            As[q][lc + 2][lr] = av.z; As[q][lc + 3][lr] = av.w;
            Bs[q][lc + 0][lr] = wv.x; Bs[q][lc + 1][lr] = wv.y;
            Bs[q][lc + 2][lr] = wv.z; Bs[q][lc + 3][lr] = wv.w;
        }
        if (t + 2 < T) {
            av = *(const float4*)(Ap + (long)(t + 2) * 8);
            wv = *(const float4*)(Wp + (long)(t + 2) * 8);
        }
#pragma unroll
        for (int k = 0; k < 8; k++) {
            float4 a0 = *(const float4*)&As[p][k][ty * 8];
            float4 a1 = *(const float4*)&As[p][k][ty * 8 + 4];
            ulonglong2 b0 = *(const ulonglong2*)&Bs[p][k][tx * 8];
            ulonglong2 b1 = *(const ulonglong2*)&Bs[p][k][tx * 8 + 4];
            unsigned long long bq[4] = {b0.x, b0.y, b1.x, b1.y};
            float ar[8] = {a0.x, a0.y, a0.z, a0.w, a1.x, a1.y, a1.z, a1.w};
            unsigned long long pa[8];
#pragma unroll
            for (int i = 0; i < 8; i++)
                asm("mov.b64 %0, {%1, %1};" : "=l"(pa[i]) : "f"(ar[i]));
#pragma unroll
            for (int i = 0; i < 8; i++)
#pragma unroll
                for (int j = 0; j < 4; j++)
                    asm("fma.rn.f32x2 %0, %1, %2, %0;"
                        : "+l"(acc[i][j]) : "l"(pa[i]), "l"(bq[j]));
        }
        __syncthreads();
        p ^= 1;
    }

#pragma unroll
    for (int i = 0; i < 8; i++) {
        long m = bm + ty * 8 + i;
#pragma unroll
        for (int j = 0; j < 4; j++) {
            long n = bn + tx * 8 + 2 * j;
            float2 v;
            asm("mov.b64 {%0, %1}, %2;" : "=f"(v.x), "=f"(v.y) : "l"(acc[i][j]));
            if (EPI == 1) { v.x = siluf(v.x); v.y = siluf(v.y); }
            else if (EPI == 2) {
                v.x = softplusf(v.x + bias[n]);
                v.y = softplusf(v.y + bias[n + 1]);
            }
            *(float2*)&C[m * (long)ldc + n] = v;
        }
    }
}

// ---------------- depthwise causal conv (K=4) + SiLU + split ------------------
__global__ void conv_kernel(const float* __restrict__ cw, const float* __restrict__ cb)
{
    int idx = blockIdx.x * blockDim.x + threadIdx.x;   // over MM*DI/2
    if (idx >= MM * DI / 2) return;
    int e = idx * 2;
    int d = e % DI;
    int m = e / DI;
    int l = m & (LL - 1);
    float a0 = cb[d], a1 = cb[d + 1];
#pragma unroll
    for (int k = 0; k < KCONV; k++) {
        int ls = l - (KCONV - 1) + k;
        if (ls >= 0) {
            const float* row = &g_P[(long)(m - (KCONV - 1) + k) * D2];
            a0 = fmaf(row[d],     cw[d * KCONV + k],       a0);
            a1 = fmaf(row[d + 1], cw[(d + 1) * KCONV + k], a1);
        }
    }
    a0 = siluf(a0); a1 = siluf(a1);
    g_HS[e] = a0; g_HS[e + 1] = a1;
    uint32_t h, lo;
    split2(a0, a1, h, lo);
    g_HSh[idx] = h; g_HSl[idx] = lo;
}

// ---------------- pad + split x_proj_w [80,1536] -> [128,1536] ----------------
__global__ void pad_xpw_kernel(const float* __restrict__ xw)
{
    int idx = blockIdx.x * blockDim.x + threadIdx.x;   // over 128*DI/2
    if (idx >= 128 * DI / 2) return;
    int e = idx * 2;
    int n = e / DI;
    int d = e % DI;
    float a0 = 0.f, a1 = 0.f;
    if (n < RR + 2 * NSTATE) { a0 = xw[n * DI + d]; a1 = xw[n * DI + d + 1]; }
    uint32_t h, lo;
    split2(a0, a1, h, lo);
    g_XPWh[idx] = h; g_XPWl[idx] = lo;
}

// ---------------- reduce split-K partials into SSMP ---------------------------
__global__ void spxsum_kernel()
{
    int idx = blockIdx.x * blockDim.x + threadIdx.x;
    if (idx >= MM * 128) return;
    float s = 0.f;
#pragma unroll
    for (int j = 0; j < NSPLIT; j++) s += g_SPX[(size_t)j * MM * 128 + idx];
    g_SSMP[idx] = s;
}

// ---------------- selective scan ----------------------------------------------
__global__ void scan_kernel(const float* __restrict__ A_log)
{
    int t = blockIdx.x * blockDim.x + threadIdx.x;
    int gid = t >> 4;
    int n = t & 15;
    if (gid >= BB * DI) return;
    int b = gid / DI;
    int d = gid - b * DI;

    float An = -__expf(A_log[d * NSTATE + n]);
    float s = 0.f;
    const float* dtp = g_DT + (long)b * LL * DI + d;
    const float* hsp = g_HS + (long)b * LL * DI + d;
    const float* sp  = g_SSMP + (long)b * LL * 128;
    float* yp = g_YS + (long)b * LL * DI + d;

    for (int l = 0; l < LL; l++) {
        float dtv = dtp[(long)l * DI];
        float hv  = hsp[(long)l * DI];
        float bv  = sp[l * 128 + RR + n];
        float cv  = sp[l * 128 + RR + NSTATE + n];
        s = fmaf(__expf(dtv * An), s, dtv * bv * hv);
        float p = s * cv;
        p += __shfl_xor_sync(0xffffffffu, p, 8);
        p += __shfl_xor_sync(0xffffffffu, p, 4);
        p += __shfl_xor_sync(0xffffffffu, p, 2);
        p += __shfl_xor_sync(0xffffffffu, p, 1);
        if (n == 0) yp[(long)l * DI] = p;
    }
}

// ---------------- combine: y = (ys + hs*D) * silu(gate), split ----------------
__global__ void combine_kernel(const float* __restrict__ Dv)
{
    int idx = blockIdx.x * blockDim.x + threadIdx.x;   // over MM*DI/2
    if (idx >= MM * DI / 2) return;
    int e = idx * 2;
    int d = e % DI;
    int m = e / DI;
    const float* gp = &g_P[(long)m * D2 + DI];
    float y0 = (g_YS[e]     + g_HS[e]     * Dv[d])     * siluf(gp[d]);
    float y1 = (g_YS[e + 1] + g_HS[e + 1] * Dv[d + 1]) * siluf(gp[d + 1]);
    uint32_t h, lo;
    split2(y0, y1, h, lo);
    g_Yh[idx] = h; g_Yl[idx] = lo;
}

// ---------------- launch ------------------------------------------------------
extern "C" void kernel_launch(void* const* d_in, const int* in_sizes, int n_in,
                              void* d_out, int out_size)
{
    const float* x    = (const float*)d_in[0];
    const float* iuw  = (const float*)d_in[1];
    const float* idw  = (const float*)d_in[2];
    const float* cw   = (const float*)d_in[3];
    const float* cb   = (const float*)d_in[4];
    const float* xpw  = (const float*)d_in[5];
    const float* dtw  = (const float*)d_in[6];
    const float* dtb  = (const float*)d_in[7];
    const float* alog = (const float*)d_in[8];
    const float* Dv   = (const float*)d_in[9];
    const float* ouw  = (const float*)d_in[10];
    const float* odw  = (const float*)d_in[11];
    float* out = (float*)d_out;

    float *P, *SPX, *SSMP, *DT;
    uint32_t *xh, *xl, *iuwh, *iuwl, *idwh, *idwl, *ouwh, *ouwl, *odwh, *odwl;
    uint32_t *T1h, *T1l, *T4h, *T4l, *Yh, *Yl, *HSh, *HSl, *XPWh, *XPWl;
    cudaGetSymbolAddress((void**)&P,    g_P);
    cudaGetSymbolAddress((void**)&SPX,  g_SPX);
    cudaGetSymbolAddress((void**)&SSMP, g_SSMP);
    cudaGetSymbolAddress((void**)&DT,   g_DT);
    cudaGetSymbolAddress((void**)&xh,   g_xh);   cudaGetSymbolAddress((void**)&xl,   g_xl);
    cudaGetSymbolAddress((void**)&iuwh, g_iuwh); cudaGetSymbolAddress((void**)&iuwl, g_iuwl);
    cudaGetSymbolAddress((void**)&idwh, g_idwh); cudaGetSymbolAddress((void**)&idwl, g_idwl);
    cudaGetSymbolAddress((void**)&ouwh, g_ouwh); cudaGetSymbolAddress((void**)&ouwl, g_ouwl);
    cudaGetSymbolAddress((void**)&odwh, g_odwh); cudaGetSymbolAddress((void**)&odwl, g_odwl);
    cudaGetSymbolAddress((void**)&T1h,  g_T1h);  cudaGetSymbolAddress((void**)&T1l,  g_T1l);
    cudaGetSymbolAddress((void**)&T4h,  g_T4h);  cudaGetSymbolAddress((void**)&T4l,  g_T4l);
    cudaGetSymbolAddress((void**)&Yh,   g_Yh);   cudaGetSymbolAddress((void**)&Yl,   g_Yl);
    cudaGetSymbolAddress((void**)&HSh,  g_HSh);  cudaGetSymbolAddress((void**)&HSl,  g_HSl);
    cudaGetSymbolAddress((void**)&XPWh, g_XPWh); cudaGetSymbolAddress((void**)&XPWl, g_XPWl);

    cudaFuncSetAttribute(hgemm_kernel<0>, cudaFuncAttributeMaxDynamicSharedMemorySize, HSMEM);
    cudaFuncSetAttribute(hgemm_kernel<2>, cudaFuncAttributeMaxDynamicSharedMemorySize, HSMEM);

    // 0) split inputs/weights into bf16 hi/lo
    split_kernel<<<(MM*HH/4 + 255)/256, 256>>>(x,   xh,   xl,   MM*HH/4);
    split_kernel<<<(D1*HH/4 + 255)/256, 256>>>(iuw, iuwh, iuwl, D1*HH/4);
    split_kernel<<<(D2*D1/4 + 255)/256, 256>>>(idw, idwh, idwl, D2*D1/4);
    split_kernel<<<(D3*DI/4 + 255)/256, 256>>>(ouw, ouwh, ouwl, D3*DI/4);
    split_kernel<<<(HH*D3/4 + 255)/256, 256>>>(odw, odwh, odwl, HH*D3/4);
    pad_xpw_kernel<<<(128*DI/2 + 255)/256, 256>>>(xpw);

    // 1) T1 = silu(x @ in_up_w^T) -> hi/lo      [2048,12288] K=768
    hgemm_kernel<2><<<dim3(D1/128, MM/128, 1), 256, HSMEM>>>(
        xh, xl, iuwh, iuwl, nullptr, T1h, T1l, HH, HH, D1, HH, 0);
    // 2) P = T1 @ in_down_w^T -> fp32           [2048,3072] K=12288
    hgemm_kernel<0><<<dim3(D2/128, MM/128, 1), 256, HSMEM>>>(
        T1h, T1l, idwh, idwl, P, nullptr, nullptr, D1, D1, D2, D1, 0);
    // 3) HS = silu(conv(hs)+b) -> fp32 + hi/lo
    conv_kernel<<<(MM*DI/2 + 255)/256, 256>>>(cw, cb);
    // 4) SSMP = HS @ XPW^T (split-K x8 + reduce)
    hgemm_kernel<0><<<dim3(1, MM/128, NSPLIT), 256, HSMEM>>>(
        HSh, HSl, XPWh, XPWl, SPX, nullptr, nullptr, DI, DI, 128, DI/NSPLIT, (long)MM*128);
    spxsum_kernel<<<(MM*128 + 255)/256, 256>>>();
    // 5) DT = softplus(SSMP[:, :48] @ dt_w^T + dt_b)
    sgemm_kernel<2><<<dim3(DI/128, MM/128), 256>>>(SSMP, dtw, dtb, DT, RR, 128, RR, DI);
    // 6) selective scan -> YS
    scan_kernel<<<(BB*DI*16 + 255)/256, 256>>>(alog);
    // 7) Y = (YS + HS*D) * silu(gate) -> hi/lo
    combine_kernel<<<(MM*DI/2 + 255)/256, 256>>>(Dv);
    // 8) T4 = silu(Y @ out_up_w^T) -> hi/lo     [2048,6144] K=1536
    hgemm_kernel<2><<<dim3(D3/128, MM/128, 1), 256, HSMEM>>>(
        Yh, Yl, ouwh, ouwl, nullptr, T4h, T4l, DI, DI, D3, DI, 0);
    // 9) out = T4 @ out_down_w^T -> fp32        [2048,768] K=6144
    hgemm_kernel<0><<<dim3(HH/128, MM/128, 1), 256, HSMEM>>>(
        T4h, T4l, odwh, odwl, out, nullptr, nullptr, D3, D3, HH, D3, 0);
}

// round 9
// speedup vs baseline: 1.0929x; 1.0929x over previous
#include <cuda_runtime.h>
#include <cstdint>

#define BB 2
#define LL 1024
#define HH 768
#define DI 1536
#define NSTATE 16
#define KCONV 4
#define RR 48
#define MM (BB*LL)          // 2048
#define D1 (2*DI*4)         // 12288
#define D2 (2*DI)           // 3072
#define D3 (4*DI)           // 6144
#define NSPLIT 8

// ---------------- scratch (device globals: no allocation allowed) --------------
__device__ float g_P [(size_t)MM*D2];
__device__ float g_HS[(size_t)MM*DI];
__device__ float g_SPX[(size_t)NSPLIT*MM*128];
__device__ float g_SSMP[(size_t)MM*128];
__device__ float g_DT[(size_t)MM*DI];
__device__ float g_YS[(size_t)MM*DI];
// bf16 hi/lo pairs, packed u32 (2 bf16 per u32)
__device__ uint32_t g_xh [(size_t)MM*HH/2],  g_xl [(size_t)MM*HH/2];
__device__ uint32_t g_iuwh[(size_t)D1*HH/2], g_iuwl[(size_t)D1*HH/2];
__device__ uint32_t g_idwh[(size_t)D2*D1/2], g_idwl[(size_t)D2*D1/2];
__device__ uint32_t g_ouwh[(size_t)D3*DI/2], g_ouwl[(size_t)D3*DI/2];
__device__ uint32_t g_odwh[(size_t)HH*D3/2], g_odwl[(size_t)HH*D3/2];
__device__ uint32_t g_T1h[(size_t)MM*D1/2],  g_T1l[(size_t)MM*D1/2];
__device__ uint32_t g_T4h[(size_t)MM*D3/2],  g_T4l[(size_t)MM*D3/2];
__device__ uint32_t g_Yh [(size_t)MM*DI/2],  g_Yl [(size_t)MM*DI/2];
__device__ uint32_t g_HSh[(size_t)MM*DI/2],  g_HSl[(size_t)MM*DI/2];
__device__ uint32_t g_XPWh[128*DI/2],        g_XPWl[128*DI/2];

__device__ __forceinline__ float siluf(float x) { return x / (1.f + __expf(-x)); }
__device__ __forceinline__ float softplusf(float x) { return (x > 20.f) ? x : log1pf(__expf(x)); }

__device__ __forceinline__ void split2(float a, float b, uint32_t& hi, uint32_t& lo) {
    uint32_t x = __float_as_uint(a), y = __float_as_uint(b);
    asm("prmt.b32 %0, %1, %2, 0x7632;" : "=r"(hi) : "r"(x), "r"(y));
    float lx = a - __uint_as_float(x & 0xFFFF0000u);
    float ly = b - __uint_as_float(y & 0xFFFF0000u);
    asm("cvt.rn.satfinite.bf16x2.f32 %0, %1, %2;" : "=r"(lo) : "f"(ly), "f"(lx));
}

__device__ __forceinline__ uint32_t smem_u32(const void* p) {
    uint32_t a;
    asm("{ .reg .u64 t; cvta.to.shared.u64 t, %1; cvt.u32.u64 %0, t; }" : "=r"(a) : "l"(p));
    return a;
}
__device__ __forceinline__ void ldsm4(uint32_t* r, uint32_t addr) {
    asm volatile("ldmatrix.sync.aligned.m8n8.x4.shared.b16 {%0,%1,%2,%3}, [%4];"
        : "=r"(r[0]), "=r"(r[1]), "=r"(r[2]), "=r"(r[3]) : "r"(addr));
}
__device__ __forceinline__ void mma_bf16(float* d, const uint32_t* a, const uint32_t* b) {
    asm volatile("mma.sync.aligned.m16n8k16.row.col.f32.bf16.bf16.f32 "
        "{%0,%1,%2,%3}, {%4,%5,%6,%7}, {%8,%9}, {%0,%1,%2,%3};"
        : "+f"(d[0]), "+f"(d[1]), "+f"(d[2]), "+f"(d[3])
        : "r"(a[0]), "r"(a[1]), "r"(a[2]), "r"(a[3]), "r"(b[0]), "r"(b[1]));
}
__device__ __forceinline__ void cpa16(uint32_t dst, const uint32_t* src) {
    asm volatile("cp.async.cg.shared.global [%0], [%1], 16;" :: "r"(dst), "l"(src) : "memory");
}

// ---------------- split pass: fp32 -> hi/lo bf16 pairs -------------------------
__global__ void split_kernel(const float* __restrict__ src, uint32_t* __restrict__ hi,
                             uint32_t* __restrict__ lo, int n4)
{
    int i = blockIdx.x * blockDim.x + threadIdx.x;
    if (i >= n4) return;
    float4 v = ((const float4*)src)[i];
    uint32_t h0, l0, h1, l1;
    split2(v.x, v.y, h0, l0);
    split2(v.z, v.w, h1, l1);
    ((uint2*)hi)[i] = make_uint2(h0, h1);
    ((uint2*)lo)[i] = make_uint2(l0, l1);
}

// ================= HMMA bf16 split GEMM: C = epi(A @ W^T) ======================
// Pre-split inputs. CTA 128x128, 256 thr, K-chunk=32, 2-stage cp.async,
// 80KB smem -> 2 CTAs/SM (cross-CTA latency hiding). regs capped at 128.
#define NST 2
#define ROWB 80u
#define TILEB (128u * ROWB)          // 10240
#define BUFB  (4u * TILEB)           // 40960
#define HSMEM (NST * BUFB)           // 81920

template<int EPI>   // 0: fp32 out, 2: silu + hi/lo bf16 out
__global__ void __launch_bounds__(256, 2) hgemm_kernel(
    const uint32_t* __restrict__ Ah, const uint32_t* __restrict__ Al,
    const uint32_t* __restrict__ Wh, const uint32_t* __restrict__ Wl,
    float* __restrict__ Cf, uint32_t* __restrict__ Ch, uint32_t* __restrict__ Cl,
    int lda, int ldw, int ldc, int kPerSplit, long csplit)
{
    extern __shared__ char smem[];
    const uint32_t sb = smem_u32(smem);
    const int tid = threadIdx.x;
    const long bm = (long)blockIdx.y * 128;
    const long bn = (long)blockIdx.x * 128;
    const int koff = blockIdx.z * kPerSplit;
    float* Cout = Cf + (long)blockIdx.z * csplit;

    // producer: thread t copies row r=t>>1, 32B-half (t&1) of each 64B tile row
    const int r = tid >> 1, half = tid & 1;
    const uint32_t soff = (uint32_t)r * ROWB + (uint32_t)half * 32u;
    const long aoff = ((bm + r) * (long)lda + koff) / 2 + half * 8;
    const long woff = ((bn + r) * (long)ldw + koff) / 2 + half * 8;
    const uint32_t* pAh = Ah + aoff;  const uint32_t* pAl = Al + aoff;
    const uint32_t* pWh = Wh + woff;  const uint32_t* pWl = Wl + woff;

#define ISSUE(tt) { long co = (long)(tt) * 16; uint32_t stb = sb + (uint32_t)((tt) & (NST-1)) * BUFB; \
    cpa16(stb + 0*TILEB + soff, pAh + co); cpa16(stb + 0*TILEB + soff + 16, pAh + co + 4); \
    cpa16(stb + 1*TILEB + soff, pAl + co); cpa16(stb + 1*TILEB + soff + 16, pAl + co + 4); \
    cpa16(stb + 2*TILEB + soff, pWh + co); cpa16(stb + 2*TILEB + soff + 16, pWh + co + 4); \
    cpa16(stb + 3*TILEB + soff, pWl + co); cpa16(stb + 3*TILEB + soff + 16, pWl + co + 4); \
    asm volatile("cp.async.commit_group;" ::: "memory"); }

    // consumer indexing (8 warps 4x2, warp tile 32x64)
    const int wid = tid >> 5, lane = tid & 31;
    const int wm = wid >> 1, wn = wid & 1;
    const uint32_t a_addr = (uint32_t)((wm * 32 + (lane & 15)) * ROWB + ((lane >> 4) << 3) * 2);
    const uint32_t b_row  = (uint32_t)(wn * 64 + (lane & 7) + ((lane >> 4) & 1) * 8);
    const uint32_t b_addr = b_row * ROWB + (uint32_t)(((lane >> 3) & 1) * 16);

    float acc[2][8][4];
#pragma unroll
    for (int f = 0; f < 2; f++)
#pragma unroll
        for (int g = 0; g < 8; g++)
#pragma unroll
            for (int e = 0; e < 4; e++) acc[f][g][e] = 0.f;

    const int Tc = kPerSplit >> 5;

    ISSUE(0);
    if (Tc > 1) ISSUE(1);

    for (int t = 0; t < Tc; t++) {
        asm volatile("cp.async.wait_group 1;" ::: "memory");
        __syncthreads();

        const uint32_t base = sb + (uint32_t)(t & (NST-1)) * BUFB;
#pragma unroll
        for (int s = 0; s < 2; s++) {
            uint32_t ah[2][4], al[2][4];
#pragma unroll
            for (int f = 0; f < 2; f++) {
                uint32_t ad = base + a_addr + (uint32_t)(f * 16) * ROWB + (uint32_t)(s * 32);
                ldsm4(ah[f], ad);
                ldsm4(al[f], ad + TILEB);
            }
#pragma unroll
            for (int g2 = 0; g2 < 4; g2++) {
                uint32_t bd = base + 2 * TILEB + b_addr + (uint32_t)(g2 * 16) * ROWB + (uint32_t)(s * 32);
                uint32_t qh[4], ql[4];
                ldsm4(qh, bd);
                ldsm4(ql, bd + TILEB);
#pragma unroll
                for (int f = 0; f < 2; f++) {
                    mma_bf16(acc[f][2*g2],   ah[f], qh);
                    mma_bf16(acc[f][2*g2],   ah[f], ql);
                    mma_bf16(acc[f][2*g2],   al[f], qh);
                    mma_bf16(acc[f][2*g2+1], ah[f], qh + 2);
                    mma_bf16(acc[f][2*g2+1], ah[f], ql + 2);
                    mma_bf16(acc[f][2*g2+1], al[f], qh + 2);
                }
            }
        }
        __syncthreads();
        if (t + 2 < Tc) ISSUE(t + 2);
    }
#undef ISSUE

    // epilogue
#pragma unroll
    for (int f = 0; f < 2; f++) {
        const long row = bm + wm * 32 + f * 16 + (lane >> 2);
#pragma unroll
        for (int g = 0; g < 8; g++) {
            const long col = bn + wn * 64 + g * 8 + (lane & 3) * 2;
            float2 v0 = {acc[f][g][0], acc[f][g][1]};
            float2 v1 = {acc[f][g][2], acc[f][g][3]};
            if (EPI == 2) {
                v0.x = siluf(v0.x); v0.y = siluf(v0.y);
                v1.x = siluf(v1.x); v1.y = siluf(v1.y);
                uint32_t h, l;
                split2(v0.x, v0.y, h, l);
                Ch[(row * (long)ldc + col) >> 1] = h;
                Cl[(row * (long)ldc + col) >> 1] = l;
                split2(v1.x, v1.y, h, l);
                Ch[((row + 8) * (long)ldc + col) >> 1] = h;
                Cl[((row + 8) * (long)ldc + col) >> 1] = l;
            } else {
                *(float2*)&Cout[row * (long)ldc + col] = v0;
                *(float2*)&Cout[(row + 8) * (long)ldc + col] = v1;
            }
        }
    }
}

// ================= scalar FFMA2 sgemm (dt GEMM, K=48) ==========================
template<int EPI>
__global__ void __launch_bounds__(256) sgemm_kernel(
    const float* __restrict__ A, const float* __restrict__ W,
    const float* __restrict__ bias, float* __restrict__ C,
    int K, int lda, int ldw, int ldc)
{
    __shared__ __align__(16) float As[2][8][128];
    __shared__ __align__(16) float Bs[2][8][128];

    const int tid = threadIdx.x;
    const long bm = (long)blockIdx.y * 128;
    const long bn = (long)blockIdx.x * 128;
    const int tx = tid & 15;
    const int ty = tid >> 4;
    const int lr = tid >> 1;
    const int lc = (tid & 1) * 4;

    const float* Ap = A + (bm + lr) * (long)lda + lc;
    const float* Wp = W + (bn + lr) * (long)ldw + lc;

    unsigned long long acc[8][4];
#pragma unroll
    for (int i = 0; i < 8; i++)
#pragma unroll
        for (int j = 0; j < 4; j++) acc[i][j] = 0ULL;

    const int T = K >> 3;
    float4 av = *(const float4*)(Ap);
    float4 wv = *(const float4*)(Wp);
    As[0][lc + 0][lr] = av.x; As[0][lc + 1][lr] = av.y;
    As[0][lc + 2][lr] = av.z; As[0][lc + 3][lr] = av.w;
    Bs[0][lc + 0][lr] = wv.x; Bs[0][lc + 1][lr] = wv.y;
    Bs[0][lc + 2][lr] = wv.z; Bs[0][lc + 3][lr] = wv.w;
    if (T > 1) { av = *(const float4*)(Ap + 8); wv = *(const float4*)(Wp + 8); }
    __syncthreads();

    int p = 0;
    for (int t = 0; t < T; t++) {
        if (t + 1 < T) {
            int q = p ^ 1;
            As[q][lc + 0][lr] = av.x; As[q][lc + 1][lr] = av.y;
            As[q][lc + 2][lr] = av.z; As[q][lc + 3][lr] = av.w;
            Bs[q][lc + 0][lr] = wv.x; Bs[q][lc + 1][lr] = wv.y;
            Bs[q][lc + 2][lr] = wv.z; Bs[q][lc + 3][lr] = wv.w;
        }
        if (t + 2 < T) {
            av = *(const float4*)(Ap + (long)(t + 2) * 8);
            wv = *(const float4*)(Wp + (long)(t + 2) * 8);
        }
#pragma unroll
        for (int k = 0; k < 8; k++) {
            float4 a0 = *(const float4*)&As[p][k][ty * 8];
            float4 a1 = *(const float4*)&As[p][k][ty * 8 + 4];
            ulonglong2 b0 = *(const ulonglong2*)&Bs[p][k][tx * 8];
            ulonglong2 b1 = *(const ulonglong2*)&Bs[p][k][tx * 8 + 4];
            unsigned long long bq[4] = {b0.x, b0.y, b1.x, b1.y};
            float ar[8] = {a0.x, a0.y, a0.z, a0.w, a1.x, a1.y, a1.z, a1.w};
            unsigned long long pa[8];
#pragma unroll
            for (int i = 0; i < 8; i++)
                asm("mov.b64 %0, {%1, %1};" : "=l"(pa[i]) : "f"(ar[i]));
#pragma unroll
            for (int i = 0; i < 8; i++)
#pragma unroll
                for (int j = 0; j < 4; j++)
                    asm("fma.rn.f32x2 %0, %1, %2, %0;"
                        : "+l"(acc[i][j]) : "l"(pa[i]), "l"(bq[j]));
        }
        __syncthreads();
        p ^= 1;
    }

#pragma unroll
    for (int i = 0; i < 8; i++) {
        long m = bm + ty * 8 + i;
#pragma unroll
        for (int j = 0; j < 4; j++) {
            long n = bn + tx * 8 + 2 * j;
            float2 v;
            asm("mov.b64 {%0, %1}, %2;" : "=f"(v.x), "=f"(v.y) : "l"(acc[i][j]));
            if (EPI == 1) { v.x = siluf(v.x); v.y = siluf(v.y); }
            else if (EPI == 2) {
                v.x = softplusf(v.x + bias[n]);
                v.y = softplusf(v.y + bias[n + 1]);
            }
            *(float2*)&C[m * (long)ldc + n] = v;
        }
    }
}

// ---------------- depthwise causal conv (K=4) + SiLU + split ------------------
__global__ void conv_kernel(const float* __restrict__ cw, const float* __restrict__ cb)
{
    int idx = blockIdx.x * blockDim.x + threadIdx.x;   // over MM*DI/2
    if (idx >= MM * DI / 2) return;
    int e = idx * 2;
    int d = e % DI;
    int m = e / DI;
    int l = m & (LL - 1);
    float a0 = cb[d], a1 = cb[d + 1];
#pragma unroll
    for (int k = 0; k < KCONV; k++) {
        int ls = l - (KCONV - 1) + k;
        if (ls >= 0) {
            const float* row = &g_P[(long)(m - (KCONV - 1) + k) * D2];
            a0 = fmaf(row[d],     cw[d * KCONV + k],       a0);
            a1 = fmaf(row[d + 1], cw[(d + 1) * KCONV + k], a1);
        }
    }
    a0 = siluf(a0); a1 = siluf(a1);
    g_HS[e] = a0; g_HS[e + 1] = a1;
    uint32_t h, lo;
    split2(a0, a1, h, lo);
    g_HSh[idx] = h; g_HSl[idx] = lo;
}

// ---------------- pad + split x_proj_w [80,1536] -> [128,1536] ----------------
__global__ void pad_xpw_kernel(const float* __restrict__ xw)
{
    int idx = blockIdx.x * blockDim.x + threadIdx.x;   // over 128*DI/2
    if (idx >= 128 * DI / 2) return;
    int e = idx * 2;
    int n = e / DI;
    int d = e % DI;
    float a0 = 0.f, a1 = 0.f;
    if (n < RR + 2 * NSTATE) { a0 = xw[n * DI + d]; a1 = xw[n * DI + d + 1]; }
    uint32_t h, lo;
    split2(a0, a1, h, lo);
    g_XPWh[idx] = h; g_XPWl[idx] = lo;
}

// ---------------- reduce split-K partials into SSMP ---------------------------
__global__ void spxsum_kernel()
{
    int idx = blockIdx.x * blockDim.x + threadIdx.x;
    if (idx >= MM * 128) return;
    float s = 0.f;
#pragma unroll
    for (int j = 0; j < NSPLIT; j++) s += g_SPX[(size_t)j * MM * 128 + idx];
    g_SSMP[idx] = s;
}

// ---------------- selective scan ----------------------------------------------
__global__ void scan_kernel(const float* __restrict__ A_log)
{
    int t = blockIdx.x * blockDim.x + threadIdx.x;
    int gid = t >> 4;
    int n = t & 15;
    if (gid >= BB * DI) return;
    int b = gid / DI;
    int d = gid - b * DI;

    float An = -__expf(A_log[d * NSTATE + n]);
    float s = 0.f;
    const float* dtp = g_DT + (long)b * LL * DI + d;
    const float* hsp = g_HS + (long)b * LL * DI + d;
    const float* sp  = g_SSMP + (long)b * LL * 128;
    float* yp = g_YS + (long)b * LL * DI + d;

    for (int l = 0; l < LL; l++) {
        float dtv = dtp[(long)l * DI];
        float hv  = hsp[(long)l * DI];
        float bv  = sp[l * 128 + RR + n];
        float cv  = sp[l * 128 + RR + NSTATE + n];
        s = fmaf(__expf(dtv * An), s, dtv * bv * hv);
        float p = s * cv;
        p += __shfl_xor_sync(0xffffffffu, p, 8);
        p += __shfl_xor_sync(0xffffffffu, p, 4);
        p += __shfl_xor_sync(0xffffffffu, p, 2);
        p += __shfl_xor_sync(0xffffffffu, p, 1);
        if (n == 0) yp[(long)l * DI] = p;
    }
}

// ---------------- combine: y = (ys + hs*D) * silu(gate), split ----------------
__global__ void combine_kernel(const float* __restrict__ Dv)
{
    int idx = blockIdx.x * blockDim.x + threadIdx.x;   // over MM*DI/2
    if (idx >= MM * DI / 2) return;
    int e = idx * 2;
    int d = e % DI;
    int m = e / DI;
    const float* gp = &g_P[(long)m * D2 + DI];
    float y0 = (g_YS[e]     + g_HS[e]     * Dv[d])     * siluf(gp[d]);
    float y1 = (g_YS[e + 1] + g_HS[e + 1] * Dv[d + 1]) * siluf(gp[d + 1]);
    uint32_t h, lo;
    split2(y0, y1, h, lo);
    g_Yh[idx] = h; g_Yl[idx] = lo;
}

// ---------------- launch ------------------------------------------------------
extern "C" void kernel_launch(void* const* d_in, const int* in_sizes, int n_in,
                              void* d_out, int out_size)
{
    const float* x    = (const float*)d_in[0];
    const float* iuw  = (const float*)d_in[1];
    const float* idw  = (const float*)d_in[2];
    const float* cw   = (const float*)d_in[3];
    const float* cb   = (const float*)d_in[4];
    const float* xpw  = (const float*)d_in[5];
    const float* dtw  = (const float*)d_in[6];
    const float* dtb  = (const float*)d_in[7];
    const float* alog = (const float*)d_in[8];
    const float* Dv   = (const float*)d_in[9];
    const float* ouw  = (const float*)d_in[10];
    const float* odw  = (const float*)d_in[11];
    float* out = (float*)d_out;

    float *P, *SPX, *SSMP, *DT;
    uint32_t *xh, *xl, *iuwh, *iuwl, *idwh, *idwl, *ouwh, *ouwl, *odwh, *odwl;
    uint32_t *T1h, *T1l, *T4h, *T4l, *Yh, *Yl, *HSh, *HSl, *XPWh, *XPWl;
    cudaGetSymbolAddress((void**)&P,    g_P);
    cudaGetSymbolAddress((void**)&SPX,  g_SPX);
    cudaGetSymbolAddress((void**)&SSMP, g_SSMP);
    cudaGetSymbolAddress((void**)&DT,   g_DT);
    cudaGetSymbolAddress((void**)&xh,   g_xh);   cudaGetSymbolAddress((void**)&xl,   g_xl);
    cudaGetSymbolAddress((void**)&iuwh, g_iuwh); cudaGetSymbolAddress((void**)&iuwl, g_iuwl);
    cudaGetSymbolAddress((void**)&idwh, g_idwh); cudaGetSymbolAddress((void**)&idwl, g_idwl);
    cudaGetSymbolAddress((void**)&ouwh, g_ouwh); cudaGetSymbolAddress((void**)&ouwl, g_ouwl);
    cudaGetSymbolAddress((void**)&odwh, g_odwh); cudaGetSymbolAddress((void**)&odwl, g_odwl);
    cudaGetSymbolAddress((void**)&T1h,  g_T1h);  cudaGetSymbolAddress((void**)&T1l,  g_T1l);
    cudaGetSymbolAddress((void**)&T4h,  g_T4h);  cudaGetSymbolAddress((void**)&T4l,  g_T4l);
    cudaGetSymbolAddress((void**)&Yh,   g_Yh);   cudaGetSymbolAddress((void**)&Yl,   g_Yl);
    cudaGetSymbolAddress((void**)&HSh,  g_HSh);  cudaGetSymbolAddress((void**)&HSl,  g_HSl);
    cudaGetSymbolAddress((void**)&XPWh, g_XPWh); cudaGetSymbolAddress((void**)&XPWl, g_XPWl);

    cudaFuncSetAttribute(hgemm_kernel<0>, cudaFuncAttributeMaxDynamicSharedMemorySize, HSMEM);
    cudaFuncSetAttribute(hgemm_kernel<2>, cudaFuncAttributeMaxDynamicSharedMemorySize, HSMEM);

    // 0) split inputs/weights into bf16 hi/lo
    split_kernel<<<(MM*HH/4 + 255)/256, 256>>>(x,   xh,   xl,   MM*HH/4);
    split_kernel<<<(D1*HH/4 + 255)/256, 256>>>(iuw, iuwh, iuwl, D1*HH/4);
    split_kernel<<<(D2*D1/4 + 255)/256, 256>>>(idw, idwh, idwl, D2*D1/4);
    split_kernel<<<(D3*DI/4 + 255)/256, 256>>>(ouw, ouwh, ouwl, D3*DI/4);
    split_kernel<<<(HH*D3/4 + 255)/256, 256>>>(odw, odwh, odwl, HH*D3/4);
    pad_xpw_kernel<<<(128*DI/2 + 255)/256, 256>>>(xpw);

    // 1) T1 = silu(x @ in_up_w^T) -> hi/lo      [2048,12288] K=768
    hgemm_kernel<2><<<dim3(D1/128, MM/128, 1), 256, HSMEM>>>(
        xh, xl, iuwh, iuwl, nullptr, T1h, T1l, HH, HH, D1, HH, 0);
    // 2) P = T1 @ in_down_w^T -> fp32           [2048,3072] K=12288
    hgemm_kernel<0><<<dim3(D2/128, MM/128, 1), 256, HSMEM>>>(
        T1h, T1l, idwh, idwl, P, nullptr, nullptr, D1, D1, D2, D1, 0);
    // 3) HS = silu(conv(hs)+b) -> fp32 + hi/lo
    conv_kernel<<<(MM*DI/2 + 255)/256, 256>>>(cw, cb);
    // 4) SSMP = HS @ XPW^T (split-K x8 + reduce)
    hgemm_kernel<0><<<dim3(1, MM/128, NSPLIT), 256, HSMEM>>>(
        HSh, HSl, XPWh, XPWl, SPX, nullptr, nullptr, DI, DI, 128, DI/NSPLIT, (long)MM*128);
    spxsum_kernel<<<(MM*128 + 255)/256, 256>>>();
    // 5) DT = softplus(SSMP[:, :48] @ dt_w^T + dt_b)
    sgemm_kernel<2><<<dim3(DI/128, MM/128), 256>>>(SSMP, dtw, dtb, DT, RR, 128, RR, DI);
    // 6) selective scan -> YS
    scan_kernel<<<(BB*DI*16 + 255)/256, 256>>>(alog);
    // 7) Y = (YS + HS*D) * silu(gate) -> hi/lo
    combine_kernel<<<(MM*DI/2 + 255)/256, 256>>>(Dv);
    // 8) T4 = silu(Y @ out_up_w^T) -> hi/lo     [2048,6144] K=1536
    hgemm_kernel<2><<<dim3(D3/128, MM/128, 1), 256, HSMEM>>>(
        Yh, Yl, ouwh, ouwl, nullptr, T4h, T4l, DI, DI, D3, DI, 0);
    // 9) out = T4 @ out_down_w^T -> fp32        [2048,768] K=6144
    hgemm_kernel<0><<<dim3(HH/128, MM/128, 1), 256, HSMEM>>>(
        T4h, T4l, odwh, odwl, out, nullptr, nullptr, D3, D3, HH, D3, 0);
}

// round 10
// speedup vs baseline: 1.4937x; 1.3667x over previous
#include <cuda_runtime.h>
#include <cuda_fp16.h>
#include <cstdint>

#define BB 2
#define LL 1024
#define HH 768
#define DI 1536
#define NSTATE 16
#define KCONV 4
#define RR 48
#define MM (BB*LL)          // 2048
#define D1 (2*DI*4)         // 12288
#define D2 (2*DI)           // 3072
#define D3 (4*DI)           // 6144
#define NSPLIT 8

// ---------------- scratch (device globals: no allocation allowed) --------------
__device__ float g_P [(size_t)MM*D2];
__device__ float g_HS[(size_t)MM*DI];
__device__ float g_SPX[(size_t)NSPLIT*MM*128];
__device__ float g_SSMP[(size_t)MM*128];
__device__ float g_DT[(size_t)MM*DI];
__device__ float g_YS[(size_t)MM*DI];
// activations: fp16 hi + fp16 residual lo (packed 2/u32). weights: single fp16.
__device__ uint32_t g_xh [(size_t)MM*HH/2],  g_xl [(size_t)MM*HH/2];
__device__ uint32_t g_iuw16[(size_t)D1*HH/2];
__device__ uint32_t g_idw16[(size_t)D2*D1/2];
__device__ uint32_t g_ouw16[(size_t)D3*DI/2];
__device__ uint32_t g_odw16[(size_t)HH*D3/2];
__device__ uint32_t g_T1h[(size_t)MM*D1/2],  g_T1l[(size_t)MM*D1/2];
__device__ uint32_t g_T4h[(size_t)MM*D3/2],  g_T4l[(size_t)MM*D3/2];
__device__ uint32_t g_Yh [(size_t)MM*DI/2],  g_Yl [(size_t)MM*DI/2];
__device__ uint32_t g_HSh[(size_t)MM*DI/2],  g_HSl[(size_t)MM*DI/2];
__device__ uint32_t g_XPW16[128*DI/2];

__device__ __forceinline__ float siluf(float x) { return x / (1.f + __expf(-x)); }
__device__ __forceinline__ float softplusf(float x) { return (x > 20.f) ? x : log1pf(__expf(x)); }

// pack two fp32 -> fp16x2 (round-to-nearest); x -> low half
__device__ __forceinline__ uint32_t cvtf16(float a, float b) {
    uint32_t r;
    asm("cvt.rn.f16x2.f32 %0, %1, %2;" : "=r"(r) : "f"(b), "f"(a));
    return r;
}
// two fp32 -> fp16x2 hi (rounded) + fp16x2 lo (residual, rounded)
__device__ __forceinline__ void splitf16(float a, float b, uint32_t& hi, uint32_t& lo) {
    hi = cvtf16(a, b);
    __half2 h = *reinterpret_cast<__half2*>(&hi);
    float ra = a - __low2float(h);
    float rb = b - __high2float(h);
    lo = cvtf16(ra, rb);
}

__device__ __forceinline__ uint32_t smem_u32(const void* p) {
    uint32_t a;
    asm("{ .reg .u64 t; cvta.to.shared.u64 t, %1; cvt.u32.u64 %0, t; }" : "=r"(a) : "l"(p));
    return a;
}
__device__ __forceinline__ void ldsm4(uint32_t* r, uint32_t addr) {
    asm volatile("ldmatrix.sync.aligned.m8n8.x4.shared.b16 {%0,%1,%2,%3}, [%4];"
        : "=r"(r[0]), "=r"(r[1]), "=r"(r[2]), "=r"(r[3]) : "r"(addr));
}
__device__ __forceinline__ void mma_f16(float* d, const uint32_t* a, const uint32_t* b) {
    asm volatile("mma.sync.aligned.m16n8k16.row.col.f32.f16.f16.f32 "
        "{%0,%1,%2,%3}, {%4,%5,%6,%7}, {%8,%9}, {%0,%1,%2,%3};"
        : "+f"(d[0]), "+f"(d[1]), "+f"(d[2]), "+f"(d[3])
        : "r"(a[0]), "r"(a[1]), "r"(a[2]), "r"(a[3]), "r"(b[0]), "r"(b[1]));
}
__device__ __forceinline__ void cpa16(uint32_t dst, const uint32_t* src) {
    asm volatile("cp.async.cg.shared.global [%0], [%1], 16;" :: "r"(dst), "l"(src) : "memory");
}

// ---------------- split pass (activations): fp32 -> fp16 hi/lo -----------------
__global__ void split_kernel(const float* __restrict__ src, uint32_t* __restrict__ hi,
                             uint32_t* __restrict__ lo, int n4)
{
    int i = blockIdx.x * blockDim.x + threadIdx.x;
    if (i >= n4) return;
    float4 v = ((const float4*)src)[i];
    uint32_t h0, l0, h1, l1;
    splitf16(v.x, v.y, h0, l0);
    splitf16(v.z, v.w, h1, l1);
    ((uint2*)hi)[i] = make_uint2(h0, h1);
    ((uint2*)lo)[i] = make_uint2(l0, l1);
}

// ---------------- convert pass (weights): fp32 -> fp16 -------------------------
__global__ void cvt_kernel(const float* __restrict__ src, uint32_t* __restrict__ dst, int n4)
{
    int i = blockIdx.x * blockDim.x + threadIdx.x;
    if (i >= n4) return;
    float4 v = ((const float4*)src)[i];
    ((uint2*)dst)[i] = make_uint2(cvtf16(v.x, v.y), cvtf16(v.z, v.w));
}

// ================= HMMA fp16 2-term GEMM: C = epi(A @ W^T) =====================
// A pre-split fp16 hi/lo; W single fp16. D = Ah*W + Al*W. CTA 128x128, 256 thr,
// K-chunk=32, 2-stage cp.async, 60KB smem -> 2+ CTAs/SM.
#define NST 2
#define ROWB 80u
#define TILEB (128u * ROWB)          // 10240
#define BUFB  (3u * TILEB)           // 30720
#define HSMEM (NST * BUFB)           // 61440

template<int EPI>   // 0: fp32 out, 2: silu + fp16 hi/lo out
__global__ void __launch_bounds__(256, 2) hgemm_kernel(
    const uint32_t* __restrict__ Ah, const uint32_t* __restrict__ Al,
    const uint32_t* __restrict__ Wh,
    float* __restrict__ Cf, uint32_t* __restrict__ Ch, uint32_t* __restrict__ Cl,
    int lda, int ldw, int ldc, int kPerSplit, long csplit)
{
    extern __shared__ char smem[];
    const uint32_t sb = smem_u32(smem);
    const int tid = threadIdx.x;
    const long bm = (long)blockIdx.y * 128;
    const long bn = (long)blockIdx.x * 128;
    const int koff = blockIdx.z * kPerSplit;
    float* Cout = Cf + (long)blockIdx.z * csplit;

    // producer: thread t copies row r=t>>1, 32B-half (t&1) of each 64B tile row
    const int r = tid >> 1, half = tid & 1;
    const uint32_t soff = (uint32_t)r * ROWB + (uint32_t)half * 32u;
    const long aoff = ((bm + r) * (long)lda + koff) / 2 + half * 8;
    const long woff = ((bn + r) * (long)ldw + koff) / 2 + half * 8;
    const uint32_t* pAh = Ah + aoff;  const uint32_t* pAl = Al + aoff;
    const uint32_t* pWh = Wh + woff;

#define ISSUE(tt) { long co = (long)(tt) * 16; uint32_t stb = sb + (uint32_t)((tt) & (NST-1)) * BUFB; \
    cpa16(stb + 0*TILEB + soff, pAh + co); cpa16(stb + 0*TILEB + soff + 16, pAh + co + 4); \
    cpa16(stb + 1*TILEB + soff, pAl + co); cpa16(stb + 1*TILEB + soff + 16, pAl + co + 4); \
    cpa16(stb + 2*TILEB + soff, pWh + co); cpa16(stb + 2*TILEB + soff + 16, pWh + co + 4); \
    asm volatile("cp.async.commit_group;" ::: "memory"); }

    // consumer indexing (8 warps 4x2, warp tile 32x64)
    const int wid = tid >> 5, lane = tid & 31;
    const int wm = wid >> 1, wn = wid & 1;
    const uint32_t a_addr = (uint32_t)((wm * 32 + (lane & 15)) * ROWB + ((lane >> 4) << 3) * 2);
    const uint32_t b_row  = (uint32_t)(wn * 64 + (lane & 7) + ((lane >> 4) & 1) * 8);
    const uint32_t b_addr = b_row * ROWB + (uint32_t)(((lane >> 3) & 1) * 16);

    float acc[2][8][4];
#pragma unroll
    for (int f = 0; f < 2; f++)
#pragma unroll
        for (int g = 0; g < 8; g++)
#pragma unroll
            for (int e = 0; e < 4; e++) acc[f][g][e] = 0.f;

    const int Tc = kPerSplit >> 5;

    ISSUE(0);
    if (Tc > 1) ISSUE(1);

    for (int t = 0; t < Tc; t++) {
        asm volatile("cp.async.wait_group 1;" ::: "memory");
        __syncthreads();

        const uint32_t base = sb + (uint32_t)(t & (NST-1)) * BUFB;
#pragma unroll
        for (int s = 0; s < 2; s++) {
            uint32_t ah[2][4], al[2][4];
#pragma unroll
            for (int f = 0; f < 2; f++) {
                uint32_t ad = base + a_addr + (uint32_t)(f * 16) * ROWB + (uint32_t)(s * 32);
                ldsm4(ah[f], ad);
                ldsm4(al[f], ad + TILEB);
            }
#pragma unroll
            for (int g2 = 0; g2 < 4; g2++) {
                uint32_t bd = base + 2 * TILEB + b_addr + (uint32_t)(g2 * 16) * ROWB + (uint32_t)(s * 32);
                uint32_t qh[4];
                ldsm4(qh, bd);
#pragma unroll
                for (int f = 0; f < 2; f++) {
                    mma_f16(acc[f][2*g2],   ah[f], qh);
                    mma_f16(acc[f][2*g2],   al[f], qh);
                    mma_f16(acc[f][2*g2+1], ah[f], qh + 2);
                    mma_f16(acc[f][2*g2+1], al[f], qh + 2);
                }
            }
        }
        __syncthreads();
        if (t + 2 < Tc) ISSUE(t + 2);
    }
#undef ISSUE

    // epilogue
#pragma unroll
    for (int f = 0; f < 2; f++) {
        const long row = bm + wm * 32 + f * 16 + (lane >> 2);
#pragma unroll
        for (int g = 0; g < 8; g++) {
            const long col = bn + wn * 64 + g * 8 + (lane & 3) * 2;
            float2 v0 = {acc[f][g][0], acc[f][g][1]};
            float2 v1 = {acc[f][g][2], acc[f][g][3]};
            if (EPI == 2) {
                v0.x = siluf(v0.x); v0.y = siluf(v0.y);
                v1.x = siluf(v1.x); v1.y = siluf(v1.y);
                uint32_t h, l;
                splitf16(v0.x, v0.y, h, l);
                Ch[(row * (long)ldc + col) >> 1] = h;
                Cl[(row * (long)ldc + col) >> 1] = l;
                splitf16(v1.x, v1.y, h, l);
                Ch[((row + 8) * (long)ldc + col) >> 1] = h;
                Cl[((row + 8) * (long)ldc + col) >> 1] = l;
            } else {
                *(float2*)&Cout[row * (long)ldc + col] = v0;
                *(float2*)&Cout[(row + 8) * (long)ldc + col] = v1;
            }
        }
    }
}

// ================= scalar FFMA2 sgemm (dt GEMM, K=48) ==========================
template<int EPI>
__global__ void __launch_bounds__(256) sgemm_kernel(
    const float* __restrict__ A, const float* __restrict__ W,
    const float* __restrict__ bias, float* __restrict__ C,
    int K, int lda, int ldw, int ldc)
{
    __shared__ __align__(16) float As[2][8][128];
    __shared__ __align__(16) float Bs[2][8][128];

    const int tid = threadIdx.x;
    const long bm = (long)blockIdx.y * 128;
    const long bn = (long)blockIdx.x * 128;
    const int tx = tid & 15;
    const int ty = tid >> 4;
    const int lr = tid >> 1;
    const int lc = (tid & 1) * 4;

    const float* Ap = A + (bm + lr) * (long)lda + lc;
    const float* Wp = W + (bn + lr) * (long)ldw + lc;

    unsigned long long acc[8][4];
#pragma unroll
    for (int i = 0; i < 8; i++)
#pragma unroll
        for (int j = 0; j < 4; j++) acc[i][j] = 0ULL;

    const int T = K >> 3;
    float4 av = *(const float4*)(Ap);
    float4 wv = *(const float4*)(Wp);
    As[0][lc + 0][lr] = av.x; As[0][lc + 1][lr] = av.y;
    As[0][lc + 2][lr] = av.z; As[0][lc + 3][lr] = av.w;
    Bs[0][lc + 0][lr] = wv.x; Bs[0][lc + 1][lr] = wv.y;
    Bs[0][lc + 2][lr] = wv.z; Bs[0][lc + 3][lr] = wv.w;
    if (T > 1) { av = *(const float4*)(Ap + 8); wv = *(const float4*)(Wp + 8); }
    __syncthreads();

    int p = 0;
    for (int t = 0; t < T; t++) {
        if (t + 1 < T) {
            int q = p ^ 1;
            As[q][lc + 0][lr] = av.x; As[q][lc + 1][lr] = av.y;
            As[q][lc + 2][lr] = av.z; As[q][lc + 3][lr] = av.w;
            Bs[q][lc + 0][lr] = wv.x; Bs[q][lc + 1][lr] = wv.y;
            Bs[q][lc + 2][lr] = wv.z; Bs[q][lc + 3][lr] = wv.w;
        }
        if (t + 2 < T) {
            av = *(const float4*)(Ap + (long)(t + 2) * 8);
            wv = *(const float4*)(Wp + (long)(t + 2) * 8);
        }
#pragma unroll
        for (int k = 0; k < 8; k++) {
            float4 a0 = *(const float4*)&As[p][k][ty * 8];
            float4 a1 = *(const float4*)&As[p][k][ty * 8 + 4];
            ulonglong2 b0 = *(const ulonglong2*)&Bs[p][k][tx * 8];
            ulonglong2 b1 = *(const ulonglong2*)&Bs[p][k][tx * 8 + 4];
            unsigned long long bq[4] = {b0.x, b0.y, b1.x, b1.y};
            float ar[8] = {a0.x, a0.y, a0.z, a0.w, a1.x, a1.y, a1.z, a1.w};
            unsigned long long pa[8];
#pragma unroll
            for (int i = 0; i < 8; i++)
                asm("mov.b64 %0, {%1, %1};" : "=l"(pa[i]) : "f"(ar[i]));
#pragma unroll
            for (int i = 0; i < 8; i++)
#pragma unroll
                for (int j = 0; j < 4; j++)
                    asm("fma.rn.f32x2 %0, %1, %2, %0;"
                        : "+l"(acc[i][j]) : "l"(pa[i]), "l"(bq[j]));
        }
        __syncthreads();
        p ^= 1;
    }

#pragma unroll
    for (int i = 0; i < 8; i++) {
        long m = bm + ty * 8 + i;
#pragma unroll
        for (int j = 0; j < 4; j++) {
            long n = bn + tx * 8 + 2 * j;
            float2 v;
            asm("mov.b64 {%0, %1}, %2;" : "=f"(v.x), "=f"(v.y) : "l"(acc[i][j]));
            if (EPI == 1) { v.x = siluf(v.x); v.y = siluf(v.y); }
            else if (EPI == 2) {
                v.x = softplusf(v.x + bias[n]);
                v.y = softplusf(v.y + bias[n + 1]);
            }
            *(float2*)&C[m * (long)ldc + n] = v;
        }
    }
}

// ---------------- depthwise causal conv (K=4) + SiLU + split ------------------
__global__ void conv_kernel(const float* __restrict__ cw, const float* __restrict__ cb)
{
    int idx = blockIdx.x * blockDim.x + threadIdx.x;   // over MM*DI/2
    if (idx >= MM * DI / 2) return;
    int e = idx * 2;
    int d = e % DI;
    int m = e / DI;
    int l = m & (LL - 1);
    float a0 = cb[d], a1 = cb[d + 1];
#pragma unroll
    for (int k = 0; k < KCONV; k++) {
        int ls = l - (KCONV - 1) + k;
        if (ls >= 0) {
            const float* row = &g_P[(long)(m - (KCONV - 1) + k) * D2];
            a0 = fmaf(row[d],     cw[d * KCONV + k],       a0);
            a1 = fmaf(row[d + 1], cw[(d + 1) * KCONV + k], a1);
        }
    }
    a0 = siluf(a0); a1 = siluf(a1);
    g_HS[e] = a0; g_HS[e + 1] = a1;
    uint32_t h, lo;
    splitf16(a0, a1, h, lo);
    g_HSh[idx] = h; g_HSl[idx] = lo;
}

// ---------------- pad + convert x_proj_w [80,1536] -> [128,1536] fp16 ---------
__global__ void pad_xpw_kernel(const float* __restrict__ xw)
{
    int idx = blockIdx.x * blockDim.x + threadIdx.x;   // over 128*DI/2
    if (idx >= 128 * DI / 2) return;
    int e = idx * 2;
    int n = e / DI;
    int d = e % DI;
    float a0 = 0.f, a1 = 0.f;
    if (n < RR + 2 * NSTATE) { a0 = xw[n * DI + d]; a1 = xw[n * DI + d + 1]; }
    g_XPW16[idx] = cvtf16(a0, a1);
}

// ---------------- reduce split-K partials into SSMP ---------------------------
__global__ void spxsum_kernel()
{
    int idx = blockIdx.x * blockDim.x + threadIdx.x;
    if (idx >= MM * 128) return;
    float s = 0.f;
#pragma unroll
    for (int j = 0; j < NSPLIT; j++) s += g_SPX[(size_t)j * MM * 128 + idx];
    g_SSMP[idx] = s;
}

// ---------------- selective scan ----------------------------------------------
__global__ void scan_kernel(const float* __restrict__ A_log)
{
    int t = blockIdx.x * blockDim.x + threadIdx.x;
    int gid = t >> 4;
    int n = t & 15;
    if (gid >= BB * DI) return;
    int b = gid / DI;
    int d = gid - b * DI;

    float An = -__expf(A_log[d * NSTATE + n]);
    float s = 0.f;
    const float* dtp = g_DT + (long)b * LL * DI + d;
    const float* hsp = g_HS + (long)b * LL * DI + d;
    const float* sp  = g_SSMP + (long)b * LL * 128;
    float* yp = g_YS + (long)b * LL * DI + d;

    for (int l = 0; l < LL; l++) {
        float dtv = dtp[(long)l * DI];
        float hv  = hsp[(long)l * DI];
        float bv  = sp[l * 128 + RR + n];
        float cv  = sp[l * 128 + RR + NSTATE + n];
        s = fmaf(__expf(dtv * An), s, dtv * bv * hv);
        float p = s * cv;
        p += __shfl_xor_sync(0xffffffffu, p, 8);
        p += __shfl_xor_sync(0xffffffffu, p, 4);
        p += __shfl_xor_sync(0xffffffffu, p, 2);
        p += __shfl_xor_sync(0xffffffffu, p, 1);
        if (n == 0) yp[(long)l * DI] = p;
    }
}

// ---------------- combine: y = (ys + hs*D) * silu(gate), split ----------------
__global__ void combine_kernel(const float* __restrict__ Dv)
{
    int idx = blockIdx.x * blockDim.x + threadIdx.x;   // over MM*DI/2
    if (idx >= MM * DI / 2) return;
    int e = idx * 2;
    int d = e % DI;
    int m = e / DI;
    const float* gp = &g_P[(long)m * D2 + DI];
    float y0 = (g_YS[e]     + g_HS[e]     * Dv[d])     * siluf(gp[d]);
    float y1 = (g_YS[e + 1] + g_HS[e + 1] * Dv[d + 1]) * siluf(gp[d + 1]);
    uint32_t h, lo;
    splitf16(y0, y1, h, lo);
    g_Yh[idx] = h; g_Yl[idx] = lo;
}

// ---------------- launch ------------------------------------------------------
extern "C" void kernel_launch(void* const* d_in, const int* in_sizes, int n_in,
                              void* d_out, int out_size)
{
    const float* x    = (const float*)d_in[0];
    const float* iuw  = (const float*)d_in[1];
    const float* idw  = (const float*)d_in[2];
    const float* cw   = (const float*)d_in[3];
    const float* cb   = (const float*)d_in[4];
    const float* xpw  = (const float*)d_in[5];
    const float* dtw  = (const float*)d_in[6];
    const float* dtb  = (const float*)d_in[7];
    const float* alog = (const float*)d_in[8];
    const float* Dv   = (const float*)d_in[9];
    const float* ouw  = (const float*)d_in[10];
    const float* odw  = (const float*)d_in[11];
    float* out = (float*)d_out;

    float *P, *SPX, *SSMP, *DT;
    uint32_t *xh, *xl, *iuw16, *idw16, *ouw16, *odw16;
    uint32_t *T1h, *T1l, *T4h, *T4l, *Yh, *Yl, *HSh, *HSl, *XPW16;
    cudaGetSymbolAddress((void**)&P,    g_P);
    cudaGetSymbolAddress((void**)&SPX,  g_SPX);
    cudaGetSymbolAddress((void**)&SSMP, g_SSMP);
    cudaGetSymbolAddress((void**)&DT,   g_DT);
    cudaGetSymbolAddress((void**)&xh,   g_xh);    cudaGetSymbolAddress((void**)&xl,   g_xl);
    cudaGetSymbolAddress((void**)&iuw16, g_iuw16);
    cudaGetSymbolAddress((void**)&idw16, g_idw16);
    cudaGetSymbolAddress((void**)&ouw16, g_ouw16);
    cudaGetSymbolAddress((void**)&odw16, g_odw16);
    cudaGetSymbolAddress((void**)&T1h,  g_T1h);   cudaGetSymbolAddress((void**)&T1l,  g_T1l);
    cudaGetSymbolAddress((void**)&T4h,  g_T4h);   cudaGetSymbolAddress((void**)&T4l,  g_T4l);
    cudaGetSymbolAddress((void**)&Yh,   g_Yh);    cudaGetSymbolAddress((void**)&Yl,   g_Yl);
    cudaGetSymbolAddress((void**)&HSh,  g_HSh);   cudaGetSymbolAddress((void**)&HSl,  g_HSl);
    cudaGetSymbolAddress((void**)&XPW16, g_XPW16);

    cudaFuncSetAttribute(hgemm_kernel<0>, cudaFuncAttributeMaxDynamicSharedMemorySize, HSMEM);
    cudaFuncSetAttribute(hgemm_kernel<2>, cudaFuncAttributeMaxDynamicSharedMemorySize, HSMEM);

    // 0) convert: x -> fp16 hi/lo; weights -> fp16
    split_kernel<<<(MM*HH/4 + 255)/256, 256>>>(x, xh, xl, MM*HH/4);
    cvt_kernel<<<(D1*HH/4 + 255)/256, 256>>>(iuw, iuw16, D1*HH/4);
    cvt_kernel<<<(D2*D1/4 + 255)/256, 256>>>(idw, idw16, D2*D1/4);
    cvt_kernel<<<(D3*DI/4 + 255)/256, 256>>>(ouw, ouw16, D3*DI/4);
    cvt_kernel<<<(HH*D3/4 + 255)/256, 256>>>(odw, odw16, HH*D3/4);
    pad_xpw_kernel<<<(128*DI/2 + 255)/256, 256>>>(xpw);

    // 1) T1 = silu(x @ in_up_w^T) -> fp16 hi/lo  [2048,12288] K=768
    hgemm_kernel<2><<<dim3(D1/128, MM/128, 1), 256, HSMEM>>>(
        xh, xl, iuw16, nullptr, T1h, T1l, HH, HH, D1, HH, 0);
    // 2) P = T1 @ in_down_w^T -> fp32            [2048,3072] K=12288
    hgemm_kernel<0><<<dim3(D2/128, MM/128, 1), 256, HSMEM>>>(
        T1h, T1l, idw16, P, nullptr, nullptr, D1, D1, D2, D1, 0);
    // 3) HS = silu(conv(hs)+b) -> fp32 + fp16 hi/lo
    conv_kernel<<<(MM*DI/2 + 255)/256, 256>>>(cw, cb);
    // 4) SSMP = HS @ XPW^T (split-K x8 + reduce)
    hgemm_kernel<0><<<dim3(1, MM/128, NSPLIT), 256, HSMEM>>>(
        HSh, HSl, XPW16, SPX, nullptr, nullptr, DI, DI, 128, DI/NSPLIT, (long)MM*128);
    spxsum_kernel<<<(MM*128 + 255)/256, 256>>>();
    // 5) DT = softplus(SSMP[:, :48] @ dt_w^T + dt_b)
    sgemm_kernel<2><<<dim3(DI/128, MM/128), 256>>>(SSMP, dtw, dtb, DT, RR, 128, RR, DI);
    // 6) selective scan -> YS
    scan_kernel<<<(BB*DI*16 + 255)/256, 256>>>(alog);
    // 7) Y = (YS + HS*D) * silu(gate) -> fp16 hi/lo
    combine_kernel<<<(MM*DI/2 + 255)/256, 256>>>(Dv);
    // 8) T4 = silu(Y @ out_up_w^T) -> fp16 hi/lo [2048,6144] K=1536
    hgemm_kernel<2><<<dim3(D3/128, MM/128, 1), 256, HSMEM>>>(
        Yh, Yl, ouw16, nullptr, T4h, T4l, DI, DI, D3, DI, 0);
    // 9) out = T4 @ out_down_w^T -> fp32         [2048,768] K=6144
    hgemm_kernel<0><<<dim3(HH/128, MM/128, 1), 256, HSMEM>>>(
        T4h, T4l, odw16, out, nullptr, nullptr, D3, D3, HH, D3, 0);
}